// round 13
// baseline (speedup 1.0000x reference)
#include <cuda_runtime.h>
#include <cuda_bf16.h>
#include <cstdint>
#include <cstddef>

#define FULLMASK 0xffffffffu
typedef unsigned long long ull;

// ---------- packed f32x2 helpers (node kernel) ----------
__device__ __forceinline__ ull pack2(float x, float y) {
    ull r; asm("mov.b64 %0, {%1,%2};" : "=l"(r) : "f"(x), "f"(y)); return r;
}
__device__ __forceinline__ void unpack2(ull v, float& x, float& y) {
    asm("mov.b64 {%0,%1}, %2;" : "=f"(x), "=f"(y) : "l"(v));
}
__device__ __forceinline__ void ffma2(ull& d, ull a, ull b) {
    asm("fma.rn.f32x2 %0, %1, %2, %0;" : "+l"(d) : "l"(a), "l"(b));
}

#define N_MAX 100000
#define E_MAX 1000000

// ---------- scratch ----------
__device__ float g_sums[(size_t)N_MAX * 64];
__device__ int   g_cnt[N_MAX];
__device__ float g_ug[64 * 128];
__device__ __nv_bfloat16 g_xb[(size_t)N_MAX * 64];   // bf16(x)
__device__ __nv_bfloat16 g_eb[(size_t)E_MAX * 32];   // bf16(ea)

__device__ __forceinline__ int clampi(int v, int hi) {
    return v < 0 ? 0 : (v >= hi ? hi - 1 : v);
}
__device__ __forceinline__ uint32_t bf2(float hi, float lo) {
    uint32_t d; asm("cvt.rn.bf16x2.f32 %0, %1, %2;" : "=r"(d) : "f"(hi), "f"(lo)); return d;
}
// m16n8k16 bf16 mma
__device__ __forceinline__ void mma_bf(float* d, uint32_t a0, uint32_t a1, uint32_t a2,
                                       uint32_t a3, uint32_t b0, uint32_t b1) {
    asm volatile("mma.sync.aligned.m16n8k16.row.col.f32.bf16.bf16.f32 "
        "{%0,%1,%2,%3}, {%4,%5,%6,%7}, {%8,%9}, {%0,%1,%2,%3};"
        : "+f"(d[0]), "+f"(d[1]), "+f"(d[2]), "+f"(d[3])
        : "r"(a0), "r"(a1), "r"(a2), "r"(a3), "r"(b0), "r"(b1));
}
__device__ __forceinline__ void cp16(uint32_t saddr, const void* g) {
    asm volatile("cp.async.cg.shared.global [%0], [%1], 16;" :: "r"(saddr), "l"(g));
}
#define CP_COMMIT() asm volatile("cp.async.commit_group;" ::: "memory")
#define CP_WAIT0()  asm volatile("cp.async.wait_group 0;" ::: "memory")

__device__ __forceinline__ uint32_t smem_u32(const void* p) {
    uint32_t a;
    asm("{ .reg .u64 t; cvta.to.shared.u64 t, %1; cvt.u32.u64 %0, t; }" : "=r"(a) : "l"(p));
    return a;
}

// ---------- zero scratch ----------
__global__ void zero_kernel(int n_nodes) {
    long long tot4 = (long long)n_nodes * 16;
    float4 z = make_float4(0.f, 0.f, 0.f, 0.f);
    float4* s4 = (float4*)g_sums;
    for (long long i = blockIdx.x * (long long)blockDim.x + threadIdx.x; i < tot4;
         i += (long long)gridDim.x * blockDim.x)
        s4[i] = z;
    for (int i = blockIdx.x * blockDim.x + threadIdx.x; i < n_nodes;
         i += gridDim.x * blockDim.x)
        g_cnt[i] = 0;
}

// ---------- ug = u @ uw1[128:160,:] ----------
__global__ void ug_kernel(const float* __restrict__ u, const float* __restrict__ uw1) {
    int g = blockIdx.x, d = threadIdx.x;
    float acc = 0.f;
#pragma unroll
    for (int k = 0; k < 32; k++)
        acc += __ldg(u + g * 32 + k) * __ldg(uw1 + (128 + k) * 128 + d);
    g_ug[g * 128 + d] = acc;
}

// ---------- cvt x, ea -> bf16 (slot-3 spacer) ----------
__global__ void cvt_kernel(const float* __restrict__ x, const float* __restrict__ ea,
                           int nx4, int ne4) {
    int stride = gridDim.x * blockDim.x;
    const float4* x4 = (const float4*)x;
    const float4* e4 = (const float4*)ea;
    uint2* xo = (uint2*)g_xb;
    uint2* eo = (uint2*)g_eb;
    for (int i = blockIdx.x * blockDim.x + threadIdx.x; i < nx4; i += stride) {
        float4 v = __ldg(x4 + i);
        xo[i] = make_uint2(bf2(v.y, v.x), bf2(v.w, v.z));
    }
    for (int i = blockIdx.x * blockDim.x + threadIdx.x; i < ne4; i += stride) {
        float4 v = __ldg(e4 + i);
        eo[i] = make_uint2(bf2(v.y, v.x), bf2(v.w, v.z));
    }
}

// ================== EDGE: bf16 m16n8k16, M=32/warp, tile=256, cp.async pipeline ==================
static constexpr int TILE_E   = 256;
static constexpr int A_BYTES  = TILE_E * 208;        // 53248 per buffer (stride 104 halves)
static constexpr int W1_B     = 2 * A_BYTES;         // 106496, [n=128][52 words]
static constexpr int W2_B     = W1_B + 128 * 208;    // 133120, [n=64][68 words]
static constexpr int B1_B     = W2_B + 64 * 272;     // 150528, f32[128]
static constexpr int B2_B     = B1_B + 512;          // 151040, f32[64]
static constexpr int ROWS_B   = B2_B + 256;          // 151296, i32[2][256]
static constexpr int COLS_B   = ROWS_B + 2048;       // 153344
static constexpr int WTS_B    = COLS_B + 2048;       // 155392
static constexpr int EDGE_SMEM = WTS_B + 2048;       // 157440 B -> 1 CTA/SM

__global__ __launch_bounds__(256, 1) void edge_mma_kernel(const int* __restrict__ ei,
                                                          const float* __restrict__ wts,
                                                          const float* __restrict__ mw1,
                                                          const float* __restrict__ mb1,
                                                          const float* __restrict__ mw2,
                                                          const float* __restrict__ mb2,
                                                          int n_edges, int n_nodes) {
    extern __shared__ char smb[];
    const uint32_t sbA = smem_u32(smb);
    uint32_t* wW1 = (uint32_t*)(smb + W1_B);
    uint32_t* wW2 = (uint32_t*)(smb + W2_B);
    float*    sB1 = (float*)(smb + B1_B);
    float*    sB2 = (float*)(smb + B2_B);
    int*    sRows = (int*)(smb + ROWS_B);
    int*    sCols = (int*)(smb + COLS_B);
    float*  sWts  = (float*)(smb + WTS_B);

    int tid = threadIdx.x, warp = tid >> 5, lane = tid & 31;
    int gid = lane >> 2, tq = lane & 3;

    // stage weights transposed [n][k] bf16 + biases (once)
    for (int idx = tid; idx < 128 * 48; idx += 256) {      // W1: n=128, k2=48
        int n = idx / 48, k2 = idx % 48;
        float lo = __ldg(mw1 + (2 * k2) * 128 + n);
        float hi = __ldg(mw1 + (2 * k2 + 1) * 128 + n);
        wW1[n * 52 + k2] = bf2(hi, lo);
    }
    for (int idx = tid; idx < 64 * 64; idx += 256) {       // W2: n=64, k2=64
        int n = idx / 64, k2 = idx % 64;
        float lo = __ldg(mw2 + (2 * k2) * 64 + n);
        float hi = __ldg(mw2 + (2 * k2 + 1) * 64 + n);
        wW2[n * 68 + k2] = bf2(hi, lo);
    }
    if (tid < 128) sB1[tid] = __ldg(mb1 + tid);
    if (tid < 64)  sB2[tid] = __ldg(mb2 + tid);

    const int eb = warp * 32;              // warp owns 32 edges (two m16 blocks)
    const int n_tiles = (n_edges + TILE_E - 1) >> 8;

    auto stage_idx = [&](int pn, int tt) {
        int e = (tt << 8) + tid;
        bool v = (e < n_edges);
        int es = v ? e : (n_edges - 1);
        sRows[pn * 256 + tid] = clampi(__ldg(ei + es), n_nodes);
        sCols[pn * 256 + tid] = v ? clampi(__ldg(ei + n_edges + es), n_nodes) : -1;
        sWts[pn * 256 + tid]  = __ldg(wts + es);
    };
    auto issue_gather = [&](int pn, int tt) {
        uint32_t base = sbA + pn * A_BYTES;
        for (int idx = tid; idx < 256 * 8; idx += 256) {   // x rows: 128B each
            int e = idx >> 3, u = idx & 7;
            int row = sRows[pn * 256 + e];
            cp16(base + e * 208 + 16 * u, g_xb + (size_t)row * 64 + 8 * u);
        }
        int e_base = tt << 8;
        for (int idx = tid; idx < 256 * 4; idx += 256) {   // ea: 64B each
            int e = idx >> 2, u = idx & 3;
            int eg = e_base + e; if (eg >= n_edges) eg = n_edges - 1;
            cp16(base + e * 208 + 128 + 16 * u, g_eb + (size_t)eg * 32 + 8 * u);
        }
    };

    int tile = blockIdx.x;
    int p = 0;
    if (tile < n_tiles) {
        stage_idx(0, tile);
        __syncthreads();
        issue_gather(0, tile);
        CP_COMMIT();
    }
    for (; tile < n_tiles; tile += gridDim.x, p ^= 1) {
        int nt = tile + gridDim.x;
        if (nt < n_tiles) stage_idx(p ^ 1, nt);
        CP_WAIT0();
        __syncthreads();
        if (nt < n_tiles) { issue_gather(p ^ 1, nt); CP_COMMIT(); }

        const uint32_t* wA = (const uint32_t*)(smb + p * A_BYTES);

        // ---- GEMM1: 6 k16-steps, 16 n-tiles, 2 m-blocks ----
        float d1[2][16][4];
#pragma unroll
        for (int mb = 0; mb < 2; mb++)
#pragma unroll
            for (int j = 0; j < 16; j++) {
                d1[mb][j][0] = d1[mb][j][1] = d1[mb][j][2] = d1[mb][j][3] = 0.f;
            }
#pragma unroll
        for (int t = 0; t < 6; t++) {
            uint32_t a[2][4];
#pragma unroll
            for (int mb = 0; mb < 2; mb++) {
                int r0 = eb + 16 * mb + gid;
                a[mb][0] = wA[r0 * 52 + 8 * t + tq];
                a[mb][1] = wA[(r0 + 8) * 52 + 8 * t + tq];
                a[mb][2] = wA[r0 * 52 + 8 * t + tq + 4];
                a[mb][3] = wA[(r0 + 8) * 52 + 8 * t + tq + 4];
            }
#pragma unroll
            for (int j = 0; j < 16; j++) {
                uint32_t b0 = wW1[(8 * j + gid) * 52 + 8 * t + tq];
                uint32_t b1 = wW1[(8 * j + gid) * 52 + 8 * t + tq + 4];
                mma_bf(d1[0][j], a[0][0], a[0][1], a[0][2], a[0][3], b0, b1);
                mma_bf(d1[1][j], a[1][0], a[1][1], a[1][2], a[1][3], b0, b1);
            }
        }

        // ---- bias + relu + pack to A2 frags (C-layout == A-layout) ----
        uint32_t a2r[2][8][4];
#pragma unroll
        for (int t2 = 0; t2 < 8; t2++) {
            int j0 = 2 * t2, j1 = 2 * t2 + 1;
            float2 bb0 = *(const float2*)(sB1 + 8 * j0 + 2 * tq);
            float2 bb1 = *(const float2*)(sB1 + 8 * j1 + 2 * tq);
#pragma unroll
            for (int mb = 0; mb < 2; mb++) {
                float c0 = fmaxf(d1[mb][j0][0] + bb0.x, 0.f);
                float c1 = fmaxf(d1[mb][j0][1] + bb0.y, 0.f);
                float c2 = fmaxf(d1[mb][j0][2] + bb0.x, 0.f);
                float c3 = fmaxf(d1[mb][j0][3] + bb0.y, 0.f);
                a2r[mb][t2][0] = bf2(c1, c0);
                a2r[mb][t2][1] = bf2(c3, c2);
                c0 = fmaxf(d1[mb][j1][0] + bb1.x, 0.f);
                c1 = fmaxf(d1[mb][j1][1] + bb1.y, 0.f);
                c2 = fmaxf(d1[mb][j1][2] + bb1.x, 0.f);
                c3 = fmaxf(d1[mb][j1][3] + bb1.y, 0.f);
                a2r[mb][t2][2] = bf2(c1, c0);
                a2r[mb][t2][3] = bf2(c3, c2);
            }
        }

        // ---- GEMM2: 8 k16-steps, 8 n-tiles, 2 m-blocks ----
        float d2[2][8][4];
#pragma unroll
        for (int mb = 0; mb < 2; mb++)
#pragma unroll
            for (int j = 0; j < 8; j++) {
                d2[mb][j][0] = d2[mb][j][1] = d2[mb][j][2] = d2[mb][j][3] = 0.f;
            }
#pragma unroll
        for (int t2 = 0; t2 < 8; t2++) {
#pragma unroll
            for (int j = 0; j < 8; j++) {
                uint32_t b0 = wW2[(8 * j + gid) * 68 + 8 * t2 + tq];
                uint32_t b1 = wW2[(8 * j + gid) * 68 + 8 * t2 + tq + 4];
                mma_bf(d2[0][j], a2r[0][t2][0], a2r[0][t2][1], a2r[0][t2][2], a2r[0][t2][3], b0, b1);
                mma_bf(d2[1][j], a2r[1][t2][0], a2r[1][t2][1], a2r[1][t2][2], a2r[1][t2][3], b0, b1);
            }
        }

        // ---- epilogue: (D2 + mb2) * w, scatter ----
#pragma unroll
        for (int mb = 0; mb < 2; mb++) {
            int r0 = eb + 16 * mb + gid;
            int c0 = sCols[p * 256 + r0], c1 = sCols[p * 256 + r0 + 8];
            float w0 = sWts[p * 256 + r0], w1 = sWts[p * 256 + r0 + 8];
#pragma unroll
            for (int j = 0; j < 8; j++) {
                float2 bb = *(const float2*)(sB2 + 8 * j + 2 * tq);
                if (c0 >= 0) {
                    float m0 = (d2[mb][j][0] + bb.x) * w0;
                    float m1 = (d2[mb][j][1] + bb.y) * w0;
                    asm volatile("red.global.add.v2.f32 [%0], {%1,%2};"
                                 :: "l"(g_sums + (size_t)c0 * 64 + 8 * j + 2 * tq),
                                    "f"(m0), "f"(m1) : "memory");
                }
                if (c1 >= 0) {
                    float m2 = (d2[mb][j][2] + bb.x) * w1;
                    float m3 = (d2[mb][j][3] + bb.y) * w1;
                    asm volatile("red.global.add.v2.f32 [%0], {%1,%2};"
                                 :: "l"(g_sums + (size_t)c1 * 64 + 8 * j + 2 * tq),
                                    "f"(m2), "f"(m3) : "memory");
                }
            }
            if (tq == 0) {
                if (c0 >= 0) atomicAdd(g_cnt + c0, 1);
                if (c1 >= 0) atomicAdd(g_cnt + c1, 1);
            }
        }
        __syncthreads();
    }
}

// ================== NODE: 4 nodes/warp, register-shfl GEMM2 (R8, proven) ==================
__global__ __launch_bounds__(256) void node_kernel(const float* __restrict__ x,
                                                   const int* __restrict__ nb,
                                                   const float* __restrict__ uw1,
                                                   const float* __restrict__ ub1,
                                                   const float* __restrict__ uw2,
                                                   const float* __restrict__ ub2,
                                                   float* __restrict__ out,
                                                   int n_nodes, int n_graphs) {
    extern __shared__ float sm[];
    float* sW1x = sm;
    float* sW1r = sm + 8192;
    float* sW2n = sm + 16384;
    float* sB1  = sm + 24576;
    for (int i = threadIdx.x; i < 8192; i += 256) {
        sW1x[i] = uw1[i];
        sW1r[i] = uw1[8192 + i];
        sW2n[i] = uw2[i];
    }
    if (threadIdx.x < 128) sB1[threadIdx.x] = ub1[threadIdx.x];
    __syncthreads();
    int warp = threadIdx.x >> 5, lane = threadIdx.x & 31;
    const int dl = lane & 15, jb = (lane >> 4) ? 64 : 0;
    const int srcBase = jb >> 2;
    const float bs0 = sB1[4 * lane], bs1 = sB1[4 * lane + 1];
    const float bs2 = sB1[4 * lane + 2], bs3 = sB1[4 * lane + 3];

    for (int n0 = (blockIdx.x * 8 + warp) * 4; n0 < n_nodes; n0 += gridDim.x * 32) {
        int nn[4]; bool vv[4];
        ull acc[4][2];
        float2 x2[4], r2[4];
#pragma unroll
        for (int k = 0; k < 4; k++) {
            vv[k] = (n0 + k < n_nodes);
            nn[k] = vv[k] ? n0 + k : n_nodes - 1;
            int b = clampi(__ldg(nb + nn[k]), n_graphs);
            float inv = 1.f / fmaxf((float)__ldg(g_cnt + nn[k]), 1.f);
            float4 ug4 = __ldg((const float4*)(g_ug + b * 128) + lane);
            acc[k][0] = pack2(bs0 + ug4.x, bs1 + ug4.y);
            acc[k][1] = pack2(bs2 + ug4.z, bs3 + ug4.w);
            x2[k] = *(const float2*)(x + (size_t)nn[k] * 64 + 2 * lane);
            float2 s2 = *(const float2*)(g_sums + (size_t)nn[k] * 64 + 2 * lane);
            r2[k] = make_float2(s2.x * inv, s2.y * inv);
        }
#pragma unroll 4
        for (int i2 = 0; i2 < 32; i2++) {
            float4 w0 = *(const float4*)(sW1x + (2 * i2) * 128 + 4 * lane);
            float4 w1 = *(const float4*)(sW1x + (2 * i2 + 1) * 128 + 4 * lane);
            float4 v0 = *(const float4*)(sW1r + (2 * i2) * 128 + 4 * lane);
            float4 v1 = *(const float4*)(sW1r + (2 * i2 + 1) * 128 + 4 * lane);
            ull wa = pack2(w0.x, w0.y), wb = pack2(w0.z, w0.w);
            ull wc = pack2(w1.x, w1.y), wd = pack2(w1.z, w1.w);
            ull va = pack2(v0.x, v0.y), vb = pack2(v0.z, v0.w);
            ull vc = pack2(v1.x, v1.y), vd = pack2(v1.z, v1.w);
#pragma unroll
            for (int k = 0; k < 4; k++) {
                float t;
                t = __shfl_sync(FULLMASK, x2[k].x, i2);
                { ull p = pack2(t, t); ffma2(acc[k][0], p, wa); ffma2(acc[k][1], p, wb); }
                t = __shfl_sync(FULLMASK, x2[k].y, i2);
                { ull p = pack2(t, t); ffma2(acc[k][0], p, wc); ffma2(acc[k][1], p, wd); }
                t = __shfl_sync(FULLMASK, r2[k].x, i2);
                { ull p = pack2(t, t); ffma2(acc[k][0], p, va); ffma2(acc[k][1], p, vb); }
                t = __shfl_sync(FULLMASK, r2[k].y, i2);
                { ull p = pack2(t, t); ffma2(acc[k][0], p, vc); ffma2(acc[k][1], p, vd); }
            }
        }
        float h[4][4];
#pragma unroll
        for (int k = 0; k < 4; k++) {
            unpack2(acc[k][0], h[k][0], h[k][1]);
            unpack2(acc[k][1], h[k][2], h[k][3]);
#pragma unroll
            for (int e = 0; e < 4; e++) h[k][e] = fmaxf(h[k][e], 0.f);
        }
        ull m[4][2];
#pragma unroll
        for (int k = 0; k < 4; k++) { m[k][0] = pack2(0.f, 0.f); m[k][1] = m[k][0]; }
#pragma unroll 4
        for (int j4 = 0; j4 < 16; j4++) {
            int d0 = jb + 4 * j4;
            int src = srcBase + j4;
            float4 wv0 = *(const float4*)(sW2n + (d0 + 0) * 64 + 4 * dl);
            float4 wv1 = *(const float4*)(sW2n + (d0 + 1) * 64 + 4 * dl);
            float4 wv2 = *(const float4*)(sW2n + (d0 + 2) * 64 + 4 * dl);
            float4 wv3 = *(const float4*)(sW2n + (d0 + 3) * 64 + 4 * dl);
            ull w0a = pack2(wv0.x, wv0.y), w0b = pack2(wv0.z, wv0.w);
            ull w1a = pack2(wv1.x, wv1.y), w1b = pack2(wv1.z, wv1.w);
            ull w2a = pack2(wv2.x, wv2.y), w2b = pack2(wv2.z, wv2.w);
            ull w3a = pack2(wv3.x, wv3.y), w3b = pack2(wv3.z, wv3.w);
#pragma unroll
            for (int k = 0; k < 4; k++) {
                float hb;
                hb = __shfl_sync(FULLMASK, h[k][0], src);
                { ull p = pack2(hb, hb); ffma2(m[k][0], p, w0a); ffma2(m[k][1], p, w0b); }
                hb = __shfl_sync(FULLMASK, h[k][1], src);
                { ull p = pack2(hb, hb); ffma2(m[k][0], p, w1a); ffma2(m[k][1], p, w1b); }
                hb = __shfl_sync(FULLMASK, h[k][2], src);
                { ull p = pack2(hb, hb); ffma2(m[k][0], p, w2a); ffma2(m[k][1], p, w2b); }
                hb = __shfl_sync(FULLMASK, h[k][3], src);
                { ull p = pack2(hb, hb); ffma2(m[k][0], p, w3a); ffma2(m[k][1], p, w3b); }
            }
        }
        float4 b2 = __ldg((const float4*)ub2 + dl);
#pragma unroll
        for (int k = 0; k < 4; k++) {
            float m0, m1, m2, m3;
            unpack2(m[k][0], m0, m1); unpack2(m[k][1], m2, m3);
            m0 += __shfl_xor_sync(FULLMASK, m0, 16);
            m1 += __shfl_xor_sync(FULLMASK, m1, 16);
            m2 += __shfl_xor_sync(FULLMASK, m2, 16);
            m3 += __shfl_xor_sync(FULLMASK, m3, 16);
            if (lane < 16 && vv[k])
                ((float4*)(out + (size_t)nn[k] * 64))[dl] =
                    make_float4(m0 + b2.x, m1 + b2.y, m2 + b2.z, m3 + b2.w);
        }
    }
}

extern "C" void kernel_launch(void* const* d_in, const int* in_sizes, int n_in,
                              void* d_out, int out_size) {
    const float* x   = (const float*)d_in[0];
    const int*   ei  = (const int*)d_in[1];
    const float* ea  = (const float*)d_in[2];
    const float* u   = (const float*)d_in[3];
    const int*   nb  = (const int*)d_in[4];
    const float* wts = (const float*)d_in[5];
    const float* mw1 = (const float*)d_in[6];
    const float* mb1 = (const float*)d_in[7];
    const float* mw2 = (const float*)d_in[8];
    const float* mb2 = (const float*)d_in[9];
    const float* uw1 = (const float*)d_in[10];
    const float* ub1 = (const float*)d_in[11];
    const float* uw2 = (const float*)d_in[12];
    const float* ub2 = (const float*)d_in[13];

    int n_nodes  = in_sizes[0] / 64;
    int n_edges  = in_sizes[2] / 32;
    int n_graphs = in_sizes[3] / 32;

    const int NODE_SMEM = 24704 * 4;   // 98816 B
    cudaFuncSetAttribute(edge_mma_kernel, cudaFuncAttributeMaxDynamicSharedMemorySize, EDGE_SMEM);
    cudaFuncSetAttribute(node_kernel, cudaFuncAttributeMaxDynamicSharedMemorySize, NODE_SMEM);

    zero_kernel<<<512, 256>>>(n_nodes);                                  // 1
    ug_kernel<<<n_graphs, 128>>>(u, uw1);                                // 2
    cvt_kernel<<<1024, 256>>>(x, ea, n_nodes * 16, n_edges * 8);         // 3 (spacer)
    edge_mma_kernel<<<148, 256, EDGE_SMEM>>>(ei, wts, mw1, mb1, mw2, mb2,
                                             n_edges, n_nodes);          // 4 (ncu slot)
    node_kernel<<<296, 256, NODE_SMEM>>>(x, nb, uw1, ub1, uw2, ub2, (float*)d_out,
                                         n_nodes, n_graphs);             // 5
}